// round 2
// baseline (speedup 1.0000x reference)
#include <cuda_runtime.h>

#define NN 50000
#define EE 400000
#define ETOT 450000   // EE + NN self loops

// ---------------- static scratch (no allocations allowed) ----------------
__device__ float  g_h1[NN * 256];        // layer1 features [N,4,64]
__device__ float4 g_asrc1[NN];           // [N,4]
__device__ float4 g_adst1[NN];           // [N,4]
__device__ float  g_h1out[NN * 64];      // layer1 output after mean+bias+ELU
__device__ float  g_h2[NN * 64];         // layer2 features
__device__ float  g_asrc2[NN];
__device__ float  g_adst2[NN];
__device__ int    g_counts[NN];
__device__ int    g_offsets[NN + 1];
__device__ int    g_cursor[NN];
__device__ int    g_csr_src[ETOT];
__device__ int    g_csr_dst[ETOT];
__device__ float4 g_ex1[ETOT];           // per-edge exp(logit), 4 heads, CSR order
__device__ float  g_ex2[ETOT];           // layer2, 1 head
__device__ float  g_u[256];              // usrc1[64](k*4+h), udst1[64], usrc2[64], udst2[64]
__device__ int    g_is64;                // edge_index dtype flag

__device__ __forceinline__ float lrelu(float v) { return v > 0.f ? v : 0.2f * v; }
__device__ __forceinline__ float elu(float v)   { return v > 0.f ? v : expm1f(v); }

// Read edge index robustly for int32 or int64 storage.
__device__ __forceinline__ int edge_val(const void* ei, int idx) {
    if (g_is64) return (int)((const long long*)ei)[idx];
    return ((const int*)ei)[idx];
}

// ---------------- detect edge_index dtype ----------------
__global__ void k_detect(const unsigned int* __restrict__ ei32) {
    if (threadIdx.x == 0) {
        int is64 = 1;
        for (int i = 0; i < 64; i++)
            if (ei32[2 * i + 1] != 0u) { is64 = 0; break; }
        g_is64 = is64;
    }
}

// ---------------- precompute folded attention vectors ----------------
__global__ void k_pre(const float* __restrict__ W1, const float* __restrict__ as1,
                      const float* __restrict__ ad1, const float* __restrict__ W2,
                      const float* __restrict__ as2, const float* __restrict__ ad2) {
    int t = threadIdx.x;              // 64 threads
    int k = t >> 2, h = t & 3;        // layer1: k in [0,16), h in [0,4)
    float s = 0.f, d = 0.f;
    for (int c = 0; c < 64; c++) {
        float w = W1[k * 256 + h * 64 + c];
        s += w * as1[h * 64 + c];
        d += w * ad1[h * 64 + c];
    }
    g_u[k * 4 + h]       = s;
    g_u[64 + k * 4 + h]  = d;
    float s2 = 0.f, d2 = 0.f;         // layer2: k = t in [0,64)
    for (int c = 0; c < 64; c++) {
        float w = W2[t * 64 + c];
        s2 += w * as2[c];
        d2 += w * ad2[c];
    }
    g_u[128 + t] = s2;
    g_u[192 + t] = d2;
}

// ---------------- CSR build ----------------
__global__ void k_zero() {
    int i = blockIdx.x * blockDim.x + threadIdx.x;
    if (i < NN) g_counts[i] = 0;
}

__global__ void k_hist(const void* __restrict__ ei) {
    int e = blockIdx.x * blockDim.x + threadIdx.x;
    if (e >= ETOT) return;
    int dst = (e < EE) ? edge_val(ei, EE + e) : (e - EE);
    atomicAdd(&g_counts[dst], 1);
}

__global__ void k_scan() {
    __shared__ int sums[1024];
    int tid = threadIdx.x;
    const int CH = (NN + 1023) / 1024;                // 49
    int beg = tid * CH;
    int end = beg + CH; if (end > NN) end = NN;
    int s = 0;
    for (int j = beg; j < end; j++) s += g_counts[j];
    sums[tid] = s;
    __syncthreads();
    for (int off = 1; off < 1024; off <<= 1) {
        int v = (tid >= off) ? sums[tid - off] : 0;
        __syncthreads();
        sums[tid] += v;
        __syncthreads();
    }
    int run = (tid == 0) ? 0 : sums[tid - 1];
    for (int j = beg; j < end; j++) {
        int c = g_counts[j];
        g_offsets[j] = run;
        g_cursor[j]  = run;
        run += c;
    }
    if (tid == 0) g_offsets[NN] = ETOT;
}

// ---------------- layer1 GEMM + attention coefficients ----------------
__global__ void k_gemm1(const float* __restrict__ x, const float* __restrict__ W1) {
    __shared__ float Ws[16 * 256];
    __shared__ float xs[64];
    int t = threadIdx.x;
    int base = blockIdx.x * 4;
    for (int i = t; i < 4096; i += 256) Ws[i] = W1[i];
    if (t < 64) xs[t] = x[base * 16 + t];
    __syncthreads();
#pragma unroll
    for (int i = 0; i < 4; i++) {
        float acc = 0.f;
#pragma unroll
        for (int k = 0; k < 16; k++) acc += xs[i * 16 + k] * Ws[k * 256 + t];
        g_h1[(base + i) * 256 + t] = acc;
    }
    if (t < 32) {
        int tt = t & 15;
        int i = tt >> 2, h = tt & 3;
        bool isdst = t >= 16;
        const float* u = g_u + (isdst ? 64 : 0);
        float a = 0.f;
#pragma unroll
        for (int k = 0; k < 16; k++) a += xs[i * 16 + k] * u[k * 4 + h];
        float* outp = isdst ? (float*)g_adst1 : (float*)g_asrc1;
        outp[(base + i) * 4 + h] = a;
    }
}

// ---------------- scatter edges to CSR + layer1 exp(logit) ----------------
__global__ void k_scatter(const void* __restrict__ ei) {
    int e = blockIdx.x * blockDim.x + threadIdx.x;
    if (e >= ETOT) return;
    int src, dst;
    if (e < EE) { src = edge_val(ei, e); dst = edge_val(ei, EE + e); }
    else        { src = e - EE; dst = e - EE; }
    int pos = atomicAdd(&g_cursor[dst], 1);
    g_csr_src[pos] = src;
    g_csr_dst[pos] = dst;
    float4 as = g_asrc1[src];
    float4 ad = g_adst1[dst];
    float4 ex;
    ex.x = expf(lrelu(as.x + ad.x));
    ex.y = expf(lrelu(as.y + ad.y));
    ex.z = expf(lrelu(as.z + ad.z));
    ex.w = expf(lrelu(as.w + ad.w));
    g_ex1[pos] = ex;
}

// ---------------- layer1 aggregation: warp per destination node ----------------
__global__ void k_agg1(const float* __restrict__ b1) {
    int warp = (blockIdx.x * blockDim.x + threadIdx.x) >> 5;
    int l = threadIdx.x & 31;
    if (warp >= NN) return;
    int n = warp;
    int p0 = g_offsets[n], p1 = g_offsets[n + 1];
    float acc[8] = {0,0,0,0,0,0,0,0};
    float den = 0.f;
    int hsel = l >> 3;      // lane's head
    for (int p = p0; p < p1; p++) {
        int src = g_csr_src[p];
        float4 ex4 = g_ex1[p];
        float exh = (hsel == 0) ? ex4.x : (hsel == 1) ? ex4.y : (hsel == 2) ? ex4.z : ex4.w;
        den += exh;
        const float4* hp = (const float4*)(g_h1 + src * 256) + l * 2;
        float4 v0 = hp[0], v1 = hp[1];
        acc[0] += exh * v0.x; acc[1] += exh * v0.y; acc[2] += exh * v0.z; acc[3] += exh * v0.w;
        acc[4] += exh * v1.x; acc[5] += exh * v1.y; acc[6] += exh * v1.z; acc[7] += exh * v1.w;
    }
    float inv = 0.25f / (den + 1e-16f);
    float r[8];
#pragma unroll
    for (int j = 0; j < 8; j++) {
        r[j] = acc[j] * inv;
        r[j] += __shfl_xor_sync(0xffffffffu, r[j], 8);
        r[j] += __shfl_xor_sync(0xffffffffu, r[j], 16);
    }
    if (l < 8) {
        float4 o0, o1;
        o0.x = elu(r[0] + b1[l * 8 + 0]);
        o0.y = elu(r[1] + b1[l * 8 + 1]);
        o0.z = elu(r[2] + b1[l * 8 + 2]);
        o0.w = elu(r[3] + b1[l * 8 + 3]);
        o1.x = elu(r[4] + b1[l * 8 + 4]);
        o1.y = elu(r[5] + b1[l * 8 + 5]);
        o1.z = elu(r[6] + b1[l * 8 + 6]);
        o1.w = elu(r[7] + b1[l * 8 + 7]);
        float4* op = (float4*)(g_h1out + n * 64) + l * 2;
        op[0] = o0;
        op[1] = o1;
    }
}

// ---------------- layer2 GEMM + attention coefficients ----------------
__global__ void k_gemm2(const float* __restrict__ W2) {
    __shared__ float Ws[64 * 64];
    __shared__ float xs[256];
    int t = threadIdx.x;
    int base = blockIdx.x * 4;
    for (int i = t; i < 4096; i += 256) Ws[i] = W2[i];
    xs[t] = g_h1out[base * 64 + t];
    __syncthreads();
    int i = t >> 6, c = t & 63;
    float acc = 0.f;
#pragma unroll
    for (int k = 0; k < 64; k++) acc += xs[i * 64 + k] * Ws[k * 64 + c];
    g_h2[(base + i) * 64 + c] = acc;
    if (t < 8) {
        int i2 = t & 3;
        bool isdst = t >= 4;
        const float* u = g_u + 128 + (isdst ? 64 : 0);
        float a = 0.f;
#pragma unroll
        for (int k = 0; k < 64; k++) a += xs[i2 * 64 + k] * u[k];
        if (isdst) g_adst2[base + i2] = a; else g_asrc2[base + i2] = a;
    }
}

// ---------------- layer2 exp(logit) over CSR positions ----------------
__global__ void k_ex2() {
    int p = blockIdx.x * blockDim.x + threadIdx.x;
    if (p >= ETOT) return;
    int s = g_csr_src[p], d = g_csr_dst[p];
    g_ex2[p] = expf(lrelu(g_asrc2[s] + g_adst2[d]));
}

// ---------------- layer2 aggregation + final output ----------------
__global__ void k_agg2(const float* __restrict__ b2, float* __restrict__ out) {
    int warp = (blockIdx.x * blockDim.x + threadIdx.x) >> 5;
    int l = threadIdx.x & 31;
    if (warp >= NN) return;
    int n = warp;
    int p0 = g_offsets[n], p1 = g_offsets[n + 1];
    float a0 = 0.f, a1 = 0.f, den = 0.f;
    for (int p = p0; p < p1; p++) {
        int src = g_csr_src[p];
        float ex = g_ex2[p];
        den += ex;
        float2 v = ((const float2*)(g_h2 + src * 64))[l];
        a0 += ex * v.x;
        a1 += ex * v.y;
    }
    float inv = 1.f / (den + 1e-16f);
    float2 o;
    o.x = elu(a0 * inv + b2[2 * l + 0]);
    o.y = elu(a1 * inv + b2[2 * l + 1]);
    ((float2*)(out + n * 64))[l] = o;
}

// ---------------- launch ----------------
extern "C" void kernel_launch(void* const* d_in, const int* in_sizes, int n_in,
                              void* d_out, int out_size) {
    const float* x   = (const float*)d_in[0];
    const void*  ei  = d_in[1];
    const float* W1  = (const float*)d_in[2];
    const float* as1 = (const float*)d_in[3];
    const float* ad1 = (const float*)d_in[4];
    const float* b1  = (const float*)d_in[5];
    const float* W2  = (const float*)d_in[6];
    const float* as2 = (const float*)d_in[7];
    const float* ad2 = (const float*)d_in[8];
    const float* b2  = (const float*)d_in[9];
    float* out = (float*)d_out;

    k_detect<<<1, 32>>>((const unsigned int*)ei);
    k_pre<<<1, 64>>>(W1, as1, ad1, W2, as2, ad2);
    k_zero<<<(NN + 255) / 256, 256>>>();
    k_hist<<<(ETOT + 255) / 256, 256>>>(ei);
    k_scan<<<1, 1024>>>();
    k_gemm1<<<NN / 4, 256>>>(x, W1);
    k_scatter<<<(ETOT + 255) / 256, 256>>>(ei);
    k_agg1<<<NN / 8, 256>>>(b1);
    k_gemm2<<<NN / 4, 256>>>(W2);
    k_ex2<<<(ETOT + 255) / 256, 256>>>();
    k_agg2<<<NN / 8, 256>>>(b2, out);
}

// round 3
// speedup vs baseline: 1.2727x; 1.2727x over previous
#include <cuda_runtime.h>

#define NN 50000
#define EE 400000
#define ETOT 450000   // EE + NN self loops

// ---------------- static scratch (no allocations allowed) ----------------
struct __align__(32) E1 { float4 ex; int src; int pad0, pad1, pad2; };

__device__ float  g_h1[NN * 256];        // layer1 features [N,4,64]
__device__ float4 g_asrc1[NN];           // [N,4]
__device__ float4 g_adst1[NN];           // [N,4]
__device__ float  g_h1out[NN * 64];      // layer1 output after mean+bias+ELU
__device__ float  g_h2[NN * 64];         // layer2 features
__device__ float  g_asrc2[NN];
__device__ float  g_adst2[NN];
__device__ int    g_counts[NN];
__device__ int    g_offsets[NN + 1];
__device__ int    g_cursor[NN];
__device__ int    g_csr_src[ETOT];
__device__ E1     g_e1[ETOT];            // per-edge {exp(logit) x4 heads, src}, CSR order
__device__ int    g_bsum[256];
__device__ int    g_boff[256];
__device__ float  g_u[256];              // usrc1[64](k*4+h), udst1[64], usrc2[64], udst2[64]
__device__ int    g_is64;                // edge_index dtype flag

__device__ __forceinline__ float lrelu(float v) { return v > 0.f ? v : 0.2f * v; }
__device__ __forceinline__ float elu(float v)   { return v > 0.f ? v : expm1f(v); }

__device__ __forceinline__ int edge_val(const void* ei, int idx) {
    if (g_is64) return (int)((const long long*)ei)[idx];
    return ((const int*)ei)[idx];
}

// ---------------- init: detect dtype + folded attention vectors + zero counts ----------------
__global__ void k_init(const unsigned int* __restrict__ ei32,
                       const float* __restrict__ W1, const float* __restrict__ as1,
                       const float* __restrict__ ad1, const float* __restrict__ W2,
                       const float* __restrict__ as2, const float* __restrict__ ad2) {
    int t = threadIdx.x;
    int b = blockIdx.x;
    if (b == 0) {
        if (t < 64) {
            int k = t >> 2, h = t & 3;        // layer1: k in [0,16), h in [0,4)
            float s = 0.f, d = 0.f;
            for (int c = 0; c < 64; c++) {
                float w = W1[k * 256 + h * 64 + c];
                s += w * as1[h * 64 + c];
                d += w * ad1[h * 64 + c];
            }
            g_u[k * 4 + h]      = s;
            g_u[64 + k * 4 + h] = d;
            float s2 = 0.f, d2 = 0.f;         // layer2
            for (int c = 0; c < 64; c++) {
                float w = W2[t * 64 + c];
                s2 += w * as2[c];
                d2 += w * ad2[c];
            }
            g_u[128 + t] = s2;
            g_u[192 + t] = d2;
        } else if (t < 96) {
            // dtype probe: if int64, odd 32-bit words of first 64 values are all zero
            int l = t - 64;
            unsigned a = ei32[2 * l + 1] | ei32[2 * (l + 32) + 1];
            unsigned nz = __ballot_sync(0xffffffffu, a != 0u);
            if (l == 0) g_is64 = (nz == 0u);
        }
    } else {
        int i = (b - 1) * 256 + t;
        if (i < NN) g_counts[i] = 0;
    }
}

// ---------------- fused: layer1 GEMM (+att coeffs) and dst histogram ----------------
__global__ void k_gemm1_hist(const float* __restrict__ x, const float* __restrict__ W1,
                             const void* __restrict__ ei) {
    __shared__ float Ws[16 * 256];
    __shared__ float xs[64];
    int t = threadIdx.x;
    int b = blockIdx.x;
    if (b < NN / 4) {
        int base = b * 4;
        for (int i = t; i < 4096; i += 256) Ws[i] = W1[i];
        if (t < 64) xs[t] = x[base * 16 + t];
        __syncthreads();
#pragma unroll
        for (int i = 0; i < 4; i++) {
            float acc = 0.f;
#pragma unroll
            for (int k = 0; k < 16; k++) acc += xs[i * 16 + k] * Ws[k * 256 + t];
            g_h1[(base + i) * 256 + t] = acc;
        }
        if (t < 32) {
            int tt = t & 15;
            int i = tt >> 2, h = tt & 3;
            bool isdst = t >= 16;
            const float* u = g_u + (isdst ? 64 : 0);
            float a = 0.f;
#pragma unroll
            for (int k = 0; k < 16; k++) a += xs[i * 16 + k] * u[k * 4 + h];
            float* outp = isdst ? (float*)g_adst1 : (float*)g_asrc1;
            outp[(base + i) * 4 + h] = a;
        }
    } else {
        int e = (b - NN / 4) * 256 + t;
        if (e < ETOT) {
            int dst = (e < EE) ? edge_val(ei, EE + e) : (e - EE);
            atomicAdd(&g_counts[dst], 1);
        }
    }
}

// ---------------- 3-phase coalesced prefix scan ----------------
__global__ void k_scan_a() {
    __shared__ int sh[256];
    int t = threadIdx.x;
    int b = blockIdx.x;
    int i = b * 256 + t;
    int c = (i < NN) ? g_counts[i] : 0;
    sh[t] = c;
    __syncthreads();
    for (int off = 1; off < 256; off <<= 1) {
        int v = (t >= off) ? sh[t - off] : 0;
        __syncthreads();
        sh[t] += v;
        __syncthreads();
    }
    int incl = sh[t];
    if (i < NN) g_offsets[i] = incl - c;     // block-local exclusive
    if (t == 255) g_bsum[b] = incl;
}

__global__ void k_scan_b(int nblocks) {
    __shared__ int sh[256];
    int t = threadIdx.x;
    int c = (t < nblocks) ? g_bsum[t] : 0;
    sh[t] = c;
    __syncthreads();
    for (int off = 1; off < 256; off <<= 1) {
        int v = (t >= off) ? sh[t - off] : 0;
        __syncthreads();
        sh[t] += v;
        __syncthreads();
    }
    if (t < nblocks) g_boff[t] = sh[t] - c;  // exclusive
}

__global__ void k_scan_c() {
    int t = threadIdx.x;
    int b = blockIdx.x;
    int i = b * 256 + t;
    if (i < NN) {
        int off = g_offsets[i] + g_boff[b];
        g_offsets[i] = off;
        g_cursor[i]  = off;
    }
    if (b == 0 && t == 0) g_offsets[NN] = ETOT;
}

// ---------------- scatter edges to CSR + layer1 exp(logit) ----------------
__global__ void k_scatter(const void* __restrict__ ei) {
    int e = blockIdx.x * blockDim.x + threadIdx.x;
    if (e >= ETOT) return;
    int src, dst;
    if (e < EE) { src = edge_val(ei, e); dst = edge_val(ei, EE + e); }
    else        { src = e - EE; dst = e - EE; }
    int pos = atomicAdd(&g_cursor[dst], 1);
    float4 as = g_asrc1[src];
    float4 ad = g_adst1[dst];
    float4 ex;
    ex.x = expf(lrelu(as.x + ad.x));
    ex.y = expf(lrelu(as.y + ad.y));
    ex.z = expf(lrelu(as.z + ad.z));
    ex.w = expf(lrelu(as.w + ad.w));
    g_e1[pos].ex  = ex;
    g_e1[pos].src = src;
    g_csr_src[pos] = src;
}

// ---------------- layer1 aggregation: warp per destination node ----------------
__global__ void k_agg1(const float* __restrict__ b1) {
    int warp = (blockIdx.x * blockDim.x + threadIdx.x) >> 5;
    int l = threadIdx.x & 31;
    if (warp >= NN) return;
    int n = warp;
    int p0 = g_offsets[n], p1 = g_offsets[n + 1];
    float acc[8] = {0,0,0,0,0,0,0,0};
    float den = 0.f;
    int hsel = l >> 3;      // lane's head
    for (int p = p0; p < p1; p++) {
        float4 ex4 = g_e1[p].ex;
        int src    = g_e1[p].src;
        float exh = (hsel == 0) ? ex4.x : (hsel == 1) ? ex4.y : (hsel == 2) ? ex4.z : ex4.w;
        den += exh;
        const float4* hp = (const float4*)(g_h1 + src * 256) + l * 2;
        float4 v0 = hp[0], v1 = hp[1];
        acc[0] += exh * v0.x; acc[1] += exh * v0.y; acc[2] += exh * v0.z; acc[3] += exh * v0.w;
        acc[4] += exh * v1.x; acc[5] += exh * v1.y; acc[6] += exh * v1.z; acc[7] += exh * v1.w;
    }
    float inv = 0.25f / (den + 1e-16f);
    float r[8];
#pragma unroll
    for (int j = 0; j < 8; j++) {
        r[j] = acc[j] * inv;
        r[j] += __shfl_xor_sync(0xffffffffu, r[j], 8);
        r[j] += __shfl_xor_sync(0xffffffffu, r[j], 16);
    }
    if (l < 8) {
        float4 o0, o1;
        o0.x = elu(r[0] + b1[l * 8 + 0]);
        o0.y = elu(r[1] + b1[l * 8 + 1]);
        o0.z = elu(r[2] + b1[l * 8 + 2]);
        o0.w = elu(r[3] + b1[l * 8 + 3]);
        o1.x = elu(r[4] + b1[l * 8 + 4]);
        o1.y = elu(r[5] + b1[l * 8 + 5]);
        o1.z = elu(r[6] + b1[l * 8 + 6]);
        o1.w = elu(r[7] + b1[l * 8 + 7]);
        float4* op = (float4*)(g_h1out + n * 64) + l * 2;
        op[0] = o0;
        op[1] = o1;
    }
}

// ---------------- layer2 GEMM + attention coefficients ----------------
__global__ void k_gemm2(const float* __restrict__ W2) {
    __shared__ float Ws[64 * 64];
    __shared__ float xs[256];
    int t = threadIdx.x;
    int base = blockIdx.x * 4;
    for (int i = t; i < 4096; i += 256) Ws[i] = W2[i];
    xs[t] = g_h1out[base * 64 + t];
    __syncthreads();
    int i = t >> 6, c = t & 63;
    float acc = 0.f;
#pragma unroll
    for (int k = 0; k < 64; k++) acc += xs[i * 64 + k] * Ws[k * 64 + c];
    g_h2[(base + i) * 64 + c] = acc;
    if (t < 8) {
        int i2 = t & 3;
        bool isdst = t >= 4;
        const float* u = g_u + 128 + (isdst ? 64 : 0);
        float a = 0.f;
#pragma unroll
        for (int k = 0; k < 64; k++) a += xs[i2 * 64 + k] * u[k];
        if (isdst) g_adst2[base + i2] = a; else g_asrc2[base + i2] = a;
    }
}

// ---------------- layer2 aggregation with inline exp (fused ex2) ----------------
__global__ void k_agg2(const float* __restrict__ b2, float* __restrict__ out) {
    int warp = (blockIdx.x * blockDim.x + threadIdx.x) >> 5;
    int l = threadIdx.x & 31;
    if (warp >= NN) return;
    int n = warp;
    int p0 = g_offsets[n], p1 = g_offsets[n + 1];
    int d = p1 - p0;
    float adst2n = g_adst2[n];

    // phase 1: lanes precompute {src, exp} for up to 64 edges (coalesced)
    int   sa0 = 0,  sa1 = 0;
    float ea0 = 0.f, ea1 = 0.f;
    if (l < d) {
        sa0 = g_csr_src[p0 + l];
        ea0 = expf(lrelu(g_asrc2[sa0] + adst2n));
    }
    if (l + 32 < d) {
        sa1 = g_csr_src[p0 + l + 32];
        ea1 = expf(lrelu(g_asrc2[sa1] + adst2n));
    }

    float a0 = 0.f, a1 = 0.f, den = 0.f;
    for (int j = 0; j < d; j++) {
        int src; float ex;
        if (j < 64) {
            src = __shfl_sync(0xffffffffu, (j < 32) ? sa0 : sa1, j & 31);
            ex  = __shfl_sync(0xffffffffu, (j < 32) ? ea0 : ea1, j & 31);
        } else {
            src = g_csr_src[p0 + j];
            ex  = expf(lrelu(g_asrc2[src] + adst2n));
        }
        den += ex;
        float2 v = ((const float2*)(g_h2 + src * 64))[l];
        a0 += ex * v.x;
        a1 += ex * v.y;
    }
    float inv = 1.f / (den + 1e-16f);
    float2 o;
    o.x = elu(a0 * inv + b2[2 * l + 0]);
    o.y = elu(a1 * inv + b2[2 * l + 1]);
    ((float2*)(out + n * 64))[l] = o;
}

// ---------------- launch ----------------
extern "C" void kernel_launch(void* const* d_in, const int* in_sizes, int n_in,
                              void* d_out, int out_size) {
    const float* x   = (const float*)d_in[0];
    const void*  ei  = d_in[1];
    const float* W1  = (const float*)d_in[2];
    const float* as1 = (const float*)d_in[3];
    const float* ad1 = (const float*)d_in[4];
    const float* b1  = (const float*)d_in[5];
    const float* W2  = (const float*)d_in[6];
    const float* as2 = (const float*)d_in[7];
    const float* ad2 = (const float*)d_in[8];
    const float* b2  = (const float*)d_in[9];
    float* out = (float*)d_out;

    const int NB = (NN + 255) / 256;                 // 196
    k_init<<<1 + NB, 256>>>((const unsigned int*)ei, W1, as1, ad1, W2, as2, ad2);
    k_gemm1_hist<<<NN / 4 + (ETOT + 255) / 256, 256>>>(x, W1, ei);
    k_scan_a<<<NB, 256>>>();
    k_scan_b<<<1, 256>>>(NB);
    k_scan_c<<<NB, 256>>>();
    k_scatter<<<(ETOT + 255) / 256, 256>>>(ei);
    k_agg1<<<NN / 8, 256>>>(b1);
    k_gemm2<<<NN / 4, 256>>>(W2);
    k_agg2<<<NN / 8, 256>>>(b2, out);
}

// round 4
// speedup vs baseline: 1.8059x; 1.4190x over previous
#include <cuda_runtime.h>
#include <cuda_fp16.h>

#define NN 50000
#define EE 400000
#define ETOT 450000            // EE + NN self loops
#define NB 196                 // ceil(NN/256)
#define G1B 782                // ceil(NN/64)

// ---------------- static scratch (no allocations allowed) ----------------
struct __align__(32) E1 { float4 ex; int src; int pad0, pad1, pad2; };

__device__ uint4  g_h1h[NN * 32];        // layer1 features fp16 [N,4,64] (32 uint4 = 256 half per node)
__device__ float4 g_asrc1[NN];           // [N,4]
__device__ float4 g_adst1[NN];           // [N,4]
__device__ float  g_h1out[NN * 64];      // layer1 output after mean+bias+ELU
__device__ float  g_h2[NN * 64];         // layer2 features
__device__ float  g_asrc2[NN];
__device__ float  g_adst2[NN];
__device__ int    g_counts[NN];
__device__ int    g_offsets[NN + 1];
__device__ int    g_cursor[NN];
__device__ int    g_csr_src[ETOT];
__device__ E1     g_e1[ETOT];            // per-edge {exp(logit) x4 heads, src}, CSR order
__device__ int    g_bsum[256];
__device__ float  g_u[256];              // usrc1[64](k*4+h), udst1[64], usrc2[64], udst2[64]
__device__ int    g_is64;                // edge_index dtype flag

__device__ __forceinline__ float lrelu(float v) { return v > 0.f ? v : 0.2f * v; }
__device__ __forceinline__ float elu(float v)   { return v > 0.f ? v : expm1f(v); }

__device__ __forceinline__ int edge_val(const void* ei, int idx) {
    if (g_is64) return (int)((const long long*)ei)[idx];
    return ((const int*)ei)[idx];
}

// ---------------- init: detect dtype + folded attention vectors + zero counts ----------------
__global__ void k_init(const unsigned int* __restrict__ ei32,
                       const float* __restrict__ W1, const float* __restrict__ as1,
                       const float* __restrict__ ad1, const float* __restrict__ W2,
                       const float* __restrict__ as2, const float* __restrict__ ad2) {
    int t = threadIdx.x;
    int b = blockIdx.x;
    if (b == 0) {
        if (t < 64) {
            int k = t >> 2, h = t & 3;
            float s = 0.f, d = 0.f;
            for (int c = 0; c < 64; c++) {
                float w = W1[k * 256 + h * 64 + c];
                s += w * as1[h * 64 + c];
                d += w * ad1[h * 64 + c];
            }
            g_u[k * 4 + h]      = s;
            g_u[64 + k * 4 + h] = d;
            float s2 = 0.f, d2 = 0.f;
            for (int c = 0; c < 64; c++) {
                float w = W2[t * 64 + c];
                s2 += w * as2[c];
                d2 += w * ad2[c];
            }
            g_u[128 + t] = s2;
            g_u[192 + t] = d2;
        } else if (t < 96) {
            int l = t - 64;
            unsigned a = ei32[2 * l + 1] | ei32[2 * (l + 32) + 1];
            unsigned nz = __ballot_sync(0xffffffffu, a != 0u);
            if (l == 0) g_is64 = (nz == 0u);
        }
    } else {
        int i = (b - 1) * 256 + t;
        if (i < NN) g_counts[i] = 0;
    }
}

// ---------------- fused: layer1 GEMM (64 nodes/block, 8x8 reg tile) + dst histogram ----------------
__global__ void k_gemm1_hist(const float* __restrict__ x, const float* __restrict__ W1,
                             const void* __restrict__ ei) {
    int t = threadIdx.x;
    int b = blockIdx.x;
    if (b < G1B) {
        __shared__ float Ws[4096];
        __shared__ float xs[1024];
        int base = b * 64;
        for (int i = t; i < 4096; i += 256) Ws[i] = W1[i];
        for (int i = t; i < 1024; i += 256) {
            int gi = base * 16 + i;
            xs[i] = (gi < NN * 16) ? x[gi] : 0.f;
        }
        __syncthreads();
        int ct = t & 31, nt = t >> 5;
        float acc[8][8];
#pragma unroll
        for (int i = 0; i < 8; i++)
#pragma unroll
            for (int j = 0; j < 8; j++) acc[i][j] = 0.f;
#pragma unroll
        for (int k = 0; k < 16; k++) {
            float4 wa = *(const float4*)&Ws[k * 256 + ct * 8];
            float4 wb = *(const float4*)&Ws[k * 256 + ct * 8 + 4];
#pragma unroll
            for (int i = 0; i < 8; i++) {
                float xv = xs[(nt * 8 + i) * 16 + k];
                acc[i][0] += xv * wa.x; acc[i][1] += xv * wa.y;
                acc[i][2] += xv * wa.z; acc[i][3] += xv * wa.w;
                acc[i][4] += xv * wb.x; acc[i][5] += xv * wb.y;
                acc[i][6] += xv * wb.z; acc[i][7] += xv * wb.w;
            }
        }
#pragma unroll
        for (int i = 0; i < 8; i++) {
            int node = base + nt * 8 + i;
            if (node < NN) {
                __half2 h0 = __floats2half2_rn(acc[i][0], acc[i][1]);
                __half2 h1 = __floats2half2_rn(acc[i][2], acc[i][3]);
                __half2 h2 = __floats2half2_rn(acc[i][4], acc[i][5]);
                __half2 h3 = __floats2half2_rn(acc[i][6], acc[i][7]);
                uint4 u;
                u.x = *(unsigned*)&h0; u.y = *(unsigned*)&h1;
                u.z = *(unsigned*)&h2; u.w = *(unsigned*)&h3;
                g_h1h[node * 32 + ct] = u;
            }
        }
        // att coefficients: thread -> (node_local = t>>2, head = t&3)
        {
            int nl = t >> 2, h = t & 3;
            int node = base + nl;
            if (node < NN) {
                float s = 0.f, d = 0.f;
#pragma unroll
                for (int k = 0; k < 16; k++) {
                    float xv = xs[nl * 16 + k];
                    s += xv * g_u[k * 4 + h];
                    d += xv * g_u[64 + k * 4 + h];
                }
                ((float*)g_asrc1)[node * 4 + h] = s;
                ((float*)g_adst1)[node * 4 + h] = d;
            }
        }
    } else {
        int e = (b - G1B) * 256 + t;
        if (e < ETOT) {
            int dst = (e < EE) ? edge_val(ei, EE + e) : (e - EE);
            atomicAdd(&g_counts[dst], 1);
        }
    }
}

// ---------------- scan: block-local exclusive + block sums ----------------
__global__ void k_scan_a() {
    __shared__ int sh[256];
    int t = threadIdx.x;
    int b = blockIdx.x;
    int i = b * 256 + t;
    int c = (i < NN) ? g_counts[i] : 0;
    sh[t] = c;
    __syncthreads();
    for (int off = 1; off < 256; off <<= 1) {
        int v = (t >= off) ? sh[t - off] : 0;
        __syncthreads();
        sh[t] += v;
        __syncthreads();
    }
    int incl = sh[t];
    if (i < NN) g_offsets[i] = incl - c;
    if (t == 255) g_bsum[b] = incl;
}

// ---------------- scan: add-back with inline top-level prefix (every block redoes it) ----------------
__global__ void k_scan_c() {
    __shared__ int sh[256];
    int t = threadIdx.x;
    int b = blockIdx.x;
    sh[t] = (t < NB) ? g_bsum[t] : 0;
    __syncthreads();
    for (int off = 1; off < 256; off <<= 1) {
        int v = (t >= off) ? sh[t - off] : 0;
        __syncthreads();
        sh[t] += v;
        __syncthreads();
    }
    int boff = (b == 0) ? 0 : sh[b - 1];
    int i = b * 256 + t;
    if (i < NN) {
        int off = g_offsets[i] + boff;
        g_offsets[i] = off;
        g_cursor[i]  = off;
    }
    if (b == 0 && t == 0) g_offsets[NN] = ETOT;
}

// ---------------- scatter edges to CSR + layer1 exp(logit) ----------------
__global__ void k_scatter(const void* __restrict__ ei) {
    int e = blockIdx.x * blockDim.x + threadIdx.x;
    if (e >= ETOT) return;
    int src, dst;
    if (e < EE) { src = edge_val(ei, e); dst = edge_val(ei, EE + e); }
    else        { src = e - EE; dst = e - EE; }
    int pos = atomicAdd(&g_cursor[dst], 1);
    float4 as = g_asrc1[src];
    float4 ad = g_adst1[dst];
    float4 ex;
    ex.x = expf(lrelu(as.x + ad.x));
    ex.y = expf(lrelu(as.y + ad.y));
    ex.z = expf(lrelu(as.z + ad.z));
    ex.w = expf(lrelu(as.w + ad.w));
    g_e1[pos].ex  = ex;
    g_e1[pos].src = src;
    g_csr_src[pos] = src;
}

// ---------------- layer1 aggregation: warp per destination node, fp16 gathers ----------------
__global__ void k_agg1(const float* __restrict__ b1) {
    int warp = (blockIdx.x * blockDim.x + threadIdx.x) >> 5;
    int l = threadIdx.x & 31;
    if (warp >= NN) return;
    int n = warp;
    int p0 = g_offsets[n], p1 = g_offsets[n + 1];
    float acc[8] = {0,0,0,0,0,0,0,0};
    float den = 0.f;
    int hsel = l >> 3;      // lane's head
    for (int p = p0; p < p1; p++) {
        float4 ex4 = g_e1[p].ex;
        int src    = g_e1[p].src;
        float exh = (hsel == 0) ? ex4.x : (hsel == 1) ? ex4.y : (hsel == 2) ? ex4.z : ex4.w;
        den += exh;
        uint4 u = g_h1h[src * 32 + l];
        __half2* hh = (__half2*)&u;
        float2 v0 = __half22float2(hh[0]);
        float2 v1 = __half22float2(hh[1]);
        float2 v2 = __half22float2(hh[2]);
        float2 v3 = __half22float2(hh[3]);
        acc[0] += exh * v0.x; acc[1] += exh * v0.y;
        acc[2] += exh * v1.x; acc[3] += exh * v1.y;
        acc[4] += exh * v2.x; acc[5] += exh * v2.y;
        acc[6] += exh * v3.x; acc[7] += exh * v3.y;
    }
    float inv = 0.25f / (den + 1e-16f);
    float r[8];
#pragma unroll
    for (int j = 0; j < 8; j++) {
        r[j] = acc[j] * inv;
        r[j] += __shfl_xor_sync(0xffffffffu, r[j], 8);
        r[j] += __shfl_xor_sync(0xffffffffu, r[j], 16);
    }
    if (l < 8) {
        float4 o0, o1;
        o0.x = elu(r[0] + b1[l * 8 + 0]);
        o0.y = elu(r[1] + b1[l * 8 + 1]);
        o0.z = elu(r[2] + b1[l * 8 + 2]);
        o0.w = elu(r[3] + b1[l * 8 + 3]);
        o1.x = elu(r[4] + b1[l * 8 + 4]);
        o1.y = elu(r[5] + b1[l * 8 + 5]);
        o1.z = elu(r[6] + b1[l * 8 + 6]);
        o1.w = elu(r[7] + b1[l * 8 + 7]);
        float4* op = (float4*)(g_h1out + n * 64) + l * 2;
        op[0] = o0;
        op[1] = o1;
    }
}

// ---------------- layer2 GEMM (64 nodes/block, 4x4 reg tile) + attention coefficients ----------------
__global__ void k_gemm2(const float* __restrict__ W2) {
    __shared__ float Ws[4096];
    __shared__ float xs[4096];
    int t = threadIdx.x;
    int base = blockIdx.x * 64;
    for (int i = t; i < 4096; i += 256) {
        Ws[i] = W2[i];
        int gi = base * 64 + i;
        xs[i] = (gi < NN * 64) ? g_h1out[gi] : 0.f;
    }
    __syncthreads();
    int ct = t & 15, nt = t >> 4;
    float acc[4][4];
#pragma unroll
    for (int i = 0; i < 4; i++)
#pragma unroll
        for (int j = 0; j < 4; j++) acc[i][j] = 0.f;
#pragma unroll 8
    for (int k = 0; k < 64; k++) {
        float4 w = *(const float4*)&Ws[k * 64 + ct * 4];
#pragma unroll
        for (int i = 0; i < 4; i++) {
            float xv = xs[(nt * 4 + i) * 64 + k];
            acc[i][0] += xv * w.x; acc[i][1] += xv * w.y;
            acc[i][2] += xv * w.z; acc[i][3] += xv * w.w;
        }
    }
#pragma unroll
    for (int i = 0; i < 4; i++) {
        int node = base + nt * 4 + i;
        if (node < NN) {
            float4 o; o.x = acc[i][0]; o.y = acc[i][1]; o.z = acc[i][2]; o.w = acc[i][3];
            *(float4*)&g_h2[node * 64 + ct * 4] = o;
        }
    }
    if (t < 128) {
        int nl = t >> 1;
        bool isdst = t & 1;
        int node = base + nl;
        if (node < NN) {
            const float* u = g_u + 128 + (isdst ? 64 : 0);
            float a = 0.f;
#pragma unroll 16
            for (int k = 0; k < 64; k++) a += xs[nl * 64 + k] * u[k];
            if (isdst) g_adst2[node] = a; else g_asrc2[node] = a;
        }
    }
}

// ---------------- layer2 aggregation with inline exp ----------------
__global__ void k_agg2(const float* __restrict__ b2, float* __restrict__ out) {
    int warp = (blockIdx.x * blockDim.x + threadIdx.x) >> 5;
    int l = threadIdx.x & 31;
    if (warp >= NN) return;
    int n = warp;
    int p0 = g_offsets[n], p1 = g_offsets[n + 1];
    int d = p1 - p0;
    float adst2n = g_adst2[n];

    int   sa0 = 0,  sa1 = 0;
    float ea0 = 0.f, ea1 = 0.f;
    if (l < d) {
        sa0 = g_csr_src[p0 + l];
        ea0 = expf(lrelu(g_asrc2[sa0] + adst2n));
    }
    if (l + 32 < d) {
        sa1 = g_csr_src[p0 + l + 32];
        ea1 = expf(lrelu(g_asrc2[sa1] + adst2n));
    }

    float a0 = 0.f, a1 = 0.f, den = 0.f;
    for (int j = 0; j < d; j++) {
        int src; float ex;
        if (j < 64) {
            src = __shfl_sync(0xffffffffu, (j < 32) ? sa0 : sa1, j & 31);
            ex  = __shfl_sync(0xffffffffu, (j < 32) ? ea0 : ea1, j & 31);
        } else {
            src = g_csr_src[p0 + j];
            ex  = expf(lrelu(g_asrc2[src] + adst2n));
        }
        den += ex;
        float2 v = ((const float2*)(g_h2 + src * 64))[l];
        a0 += ex * v.x;
        a1 += ex * v.y;
    }
    float inv = 1.f / (den + 1e-16f);
    float2 o;
    o.x = elu(a0 * inv + b2[2 * l + 0]);
    o.y = elu(a1 * inv + b2[2 * l + 1]);
    ((float2*)(out + n * 64))[l] = o;
}

// ---------------- launch ----------------
extern "C" void kernel_launch(void* const* d_in, const int* in_sizes, int n_in,
                              void* d_out, int out_size) {
    const float* x   = (const float*)d_in[0];
    const void*  ei  = d_in[1];
    const float* W1  = (const float*)d_in[2];
    const float* as1 = (const float*)d_in[3];
    const float* ad1 = (const float*)d_in[4];
    const float* b1  = (const float*)d_in[5];
    const float* W2  = (const float*)d_in[6];
    const float* as2 = (const float*)d_in[7];
    const float* ad2 = (const float*)d_in[8];
    const float* b2  = (const float*)d_in[9];
    float* out = (float*)d_out;

    k_init<<<1 + NB, 256>>>((const unsigned int*)ei, W1, as1, ad1, W2, as2, ad2);
    k_gemm1_hist<<<G1B + (ETOT + 255) / 256, 256>>>(x, W1, ei);
    k_scan_a<<<NB, 256>>>();
    k_scan_c<<<NB, 256>>>();
    k_scatter<<<(ETOT + 255) / 256, 256>>>(ei);
    k_agg1<<<NN / 8, 256>>>(b1);
    k_gemm2<<<G1B, 256>>>(W2);
    k_agg2<<<NN / 8, 256>>>(b2, out);
}

// round 6
// speedup vs baseline: 1.9314x; 1.0695x over previous
#include <cuda_runtime.h>
#include <cuda_fp16.h>

#define NN 50000
#define EE 400000
#define ETOT 450000            // EE + NN self loops
#define NB 196                 // ceil(NN/256)
#define G1B 782                // ceil(NN/64)

// ---------------- static scratch (no allocations allowed) ----------------
__device__ uint4    g_h1h[NN * 32];      // layer1 features fp16 [N,4,64]
__device__ float4   g_asrc1[NN];         // [N,4]
__device__ float4   g_adst1[NN];         // [N,4]
__device__ float    g_h1out[NN * 64];    // layer1 output after mean+bias+ELU
__device__ unsigned g_h2h[NN * 32];      // layer2 features fp16 [N,64] as 32 half2 words/node
__device__ float    g_asrc2[NN];
__device__ float    g_adst2[NN];
__device__ int      g_counts[NN];
__device__ int      g_offsets[NN + 1];
__device__ int      g_cursor[NN];
__device__ int      g_csr_src[ETOT];
__device__ int      g_bsum[256];
__device__ float    g_u[256];            // usrc1[64](k*4+h), udst1[64], usrc2[64], udst2[64]
__device__ int      g_is64;              // edge_index dtype flag

__device__ __forceinline__ float lrelu(float v) { return v > 0.f ? v : 0.2f * v; }
__device__ __forceinline__ float elu(float v)   { return v > 0.f ? v : expm1f(v); }

__device__ __forceinline__ int edge_val(const void* ei, int idx) {
    if (g_is64) return (int)((const long long*)ei)[idx];
    return ((const int*)ei)[idx];
}

__device__ __forceinline__ float pick4(float4 v, int s) {
    return (s == 0) ? v.x : (s == 1) ? v.y : (s == 2) ? v.z : v.w;
}

// ---------------- init: detect dtype + folded attention vectors + zero counts ----------------
__global__ void k_init(const unsigned int* __restrict__ ei32,
                       const float* __restrict__ W1, const float* __restrict__ as1,
                       const float* __restrict__ ad1, const float* __restrict__ W2,
                       const float* __restrict__ as2, const float* __restrict__ ad2) {
    int t = threadIdx.x;
    int b = blockIdx.x;
    if (b == 0) {
        if (t < 64) {
            int k = t >> 2, h = t & 3;
            float s = 0.f, d = 0.f;
            for (int c = 0; c < 64; c++) {
                float w = W1[k * 256 + h * 64 + c];
                s += w * as1[h * 64 + c];
                d += w * ad1[h * 64 + c];
            }
            g_u[k * 4 + h]      = s;
            g_u[64 + k * 4 + h] = d;
            float s2 = 0.f, d2 = 0.f;
            for (int c = 0; c < 64; c++) {
                float w = W2[t * 64 + c];
                s2 += w * as2[c];
                d2 += w * ad2[c];
            }
            g_u[128 + t] = s2;
            g_u[192 + t] = d2;
        } else if (t < 96) {
            int l = t - 64;
            unsigned a = ei32[2 * l + 1] | ei32[2 * (l + 32) + 1];
            unsigned nz = __ballot_sync(0xffffffffu, a != 0u);
            if (l == 0) g_is64 = (nz == 0u);
        }
    } else {
        int i = (b - 1) * 256 + t;
        if (i < NN) g_counts[i] = 0;
    }
}

// ---------------- fused: layer1 GEMM (64 nodes/block, 8x8 reg tile) + dst histogram ----------------
__global__ void k_gemm1_hist(const float* __restrict__ x, const float* __restrict__ W1,
                             const void* __restrict__ ei) {
    int t = threadIdx.x;
    int b = blockIdx.x;
    if (b < G1B) {
        __shared__ float Ws[4096];
        __shared__ float xs[1024];
        int base = b * 64;
        for (int i = t; i < 4096; i += 256) Ws[i] = W1[i];
        for (int i = t; i < 1024; i += 256) {
            int gi = base * 16 + i;
            xs[i] = (gi < NN * 16) ? x[gi] : 0.f;
        }
        __syncthreads();
        int ct = t & 31, nt = t >> 5;
        float acc[8][8];
#pragma unroll
        for (int i = 0; i < 8; i++)
#pragma unroll
            for (int j = 0; j < 8; j++) acc[i][j] = 0.f;
#pragma unroll
        for (int k = 0; k < 16; k++) {
            float4 wa = *(const float4*)&Ws[k * 256 + ct * 8];
            float4 wb = *(const float4*)&Ws[k * 256 + ct * 8 + 4];
#pragma unroll
            for (int i = 0; i < 8; i++) {
                float xv = xs[(nt * 8 + i) * 16 + k];
                acc[i][0] += xv * wa.x; acc[i][1] += xv * wa.y;
                acc[i][2] += xv * wa.z; acc[i][3] += xv * wa.w;
                acc[i][4] += xv * wb.x; acc[i][5] += xv * wb.y;
                acc[i][6] += xv * wb.z; acc[i][7] += xv * wb.w;
            }
        }
#pragma unroll
        for (int i = 0; i < 8; i++) {
            int node = base + nt * 8 + i;
            if (node < NN) {
                __half2 h0 = __floats2half2_rn(acc[i][0], acc[i][1]);
                __half2 h1 = __floats2half2_rn(acc[i][2], acc[i][3]);
                __half2 h2 = __floats2half2_rn(acc[i][4], acc[i][5]);
                __half2 h3 = __floats2half2_rn(acc[i][6], acc[i][7]);
                uint4 u;
                u.x = *(unsigned*)&h0; u.y = *(unsigned*)&h1;
                u.z = *(unsigned*)&h2; u.w = *(unsigned*)&h3;
                g_h1h[node * 32 + ct] = u;
            }
        }
        {
            int nl = t >> 2, h = t & 3;
            int node = base + nl;
            if (node < NN) {
                float s = 0.f, d = 0.f;
#pragma unroll
                for (int k = 0; k < 16; k++) {
                    float xv = xs[nl * 16 + k];
                    s += xv * g_u[k * 4 + h];
                    d += xv * g_u[64 + k * 4 + h];
                }
                ((float*)g_asrc1)[node * 4 + h] = s;
                ((float*)g_adst1)[node * 4 + h] = d;
            }
        }
    } else {
        int e = (b - G1B) * 256 + t;
        if (e < ETOT) {
            int dst = (e < EE) ? edge_val(ei, EE + e) : (e - EE);
            atomicAdd(&g_counts[dst], 1);
        }
    }
}

// ---------------- scan: block-local exclusive + block sums ----------------
__global__ void k_scan_a() {
    __shared__ int sh[256];
    int t = threadIdx.x;
    int b = blockIdx.x;
    int i = b * 256 + t;
    int c = (i < NN) ? g_counts[i] : 0;
    sh[t] = c;
    __syncthreads();
    for (int off = 1; off < 256; off <<= 1) {
        int v = (t >= off) ? sh[t - off] : 0;
        __syncthreads();
        sh[t] += v;
        __syncthreads();
    }
    int incl = sh[t];
    if (i < NN) g_offsets[i] = incl - c;
    if (t == 255) g_bsum[b] = incl;
}

// ---------------- scan: add-back with inline top-level prefix ----------------
__global__ void k_scan_c() {
    __shared__ int sh[256];
    int t = threadIdx.x;
    int b = blockIdx.x;
    sh[t] = (t < NB) ? g_bsum[t] : 0;
    __syncthreads();
    for (int off = 1; off < 256; off <<= 1) {
        int v = (t >= off) ? sh[t - off] : 0;
        __syncthreads();
        sh[t] += v;
        __syncthreads();
    }
    int boff = (b == 0) ? 0 : sh[b - 1];
    int i = b * 256 + t;
    if (i < NN) {
        int off = g_offsets[i] + boff;
        g_offsets[i] = off;
        g_cursor[i]  = off;
    }
    if (b == 0 && t == 0) g_offsets[NN] = ETOT;
}

// ---------------- scatter edges to CSR (src only) ----------------
__global__ void k_scatter(const void* __restrict__ ei) {
    int e = blockIdx.x * blockDim.x + threadIdx.x;
    if (e >= ETOT) return;
    int src, dst;
    if (e < EE) { src = edge_val(ei, e); dst = edge_val(ei, EE + e); }
    else        { src = e - EE; dst = e - EE; }
    int pos = atomicAdd(&g_cursor[dst], 1);
    g_csr_src[pos] = src;
}

// ---------------- layer1 aggregation: warp per node, inline exp, fp16 gathers ----------------
__global__ void k_agg1(const float* __restrict__ b1) {
    int warp = (blockIdx.x * blockDim.x + threadIdx.x) >> 5;
    int l = threadIdx.x & 31;
    if (warp >= NN) return;
    int n = warp;
    int p0 = g_offsets[n], p1 = g_offsets[n + 1];
    int d = p1 - p0;
    int hsel = l >> 3;
    float adh = pick4(g_adst1[n], hsel);

    int sa0 = 0, sa1 = 0;
    if (l < d)      sa0 = g_csr_src[p0 + l];
    if (l + 32 < d) sa1 = g_csr_src[p0 + l + 32];

    float acc[8] = {0,0,0,0,0,0,0,0};
    float den = 0.f;
    int dmain = d < 64 ? d : 64;
#pragma unroll 4
    for (int j = 0; j < dmain; j++) {
        int src = __shfl_sync(0xffffffffu, (j < 32) ? sa0 : sa1, j & 31);
        float ash = pick4(__ldg(&g_asrc1[src]), hsel);
        float exh = expf(lrelu(ash + adh));
        den += exh;
        uint4 u = g_h1h[src * 32 + l];
        __half2* hh = (__half2*)&u;
        float2 v0 = __half22float2(hh[0]);
        float2 v1 = __half22float2(hh[1]);
        float2 v2 = __half22float2(hh[2]);
        float2 v3 = __half22float2(hh[3]);
        acc[0] += exh * v0.x; acc[1] += exh * v0.y;
        acc[2] += exh * v1.x; acc[3] += exh * v1.y;
        acc[4] += exh * v2.x; acc[5] += exh * v2.y;
        acc[6] += exh * v3.x; acc[7] += exh * v3.y;
    }
    for (int j = 64; j < d; j++) {
        int src = g_csr_src[p0 + j];
        float ash = pick4(__ldg(&g_asrc1[src]), hsel);
        float exh = expf(lrelu(ash + adh));
        den += exh;
        uint4 u = g_h1h[src * 32 + l];
        __half2* hh = (__half2*)&u;
        float2 v0 = __half22float2(hh[0]);
        float2 v1 = __half22float2(hh[1]);
        float2 v2 = __half22float2(hh[2]);
        float2 v3 = __half22float2(hh[3]);
        acc[0] += exh * v0.x; acc[1] += exh * v0.y;
        acc[2] += exh * v1.x; acc[3] += exh * v1.y;
        acc[4] += exh * v2.x; acc[5] += exh * v2.y;
        acc[6] += exh * v3.x; acc[7] += exh * v3.y;
    }
    float inv = 0.25f / (den + 1e-16f);
    float r[8];
#pragma unroll
    for (int j = 0; j < 8; j++) {
        r[j] = acc[j] * inv;
        r[j] += __shfl_xor_sync(0xffffffffu, r[j], 8);
        r[j] += __shfl_xor_sync(0xffffffffu, r[j], 16);
    }
    if (l < 8) {
        float4 o0, o1;
        o0.x = elu(r[0] + b1[l * 8 + 0]);
        o0.y = elu(r[1] + b1[l * 8 + 1]);
        o0.z = elu(r[2] + b1[l * 8 + 2]);
        o0.w = elu(r[3] + b1[l * 8 + 3]);
        o1.x = elu(r[4] + b1[l * 8 + 4]);
        o1.y = elu(r[5] + b1[l * 8 + 5]);
        o1.z = elu(r[6] + b1[l * 8 + 6]);
        o1.w = elu(r[7] + b1[l * 8 + 7]);
        float4* op = (float4*)(g_h1out + n * 64) + l * 2;
        op[0] = o0;
        op[1] = o1;
    }
}

// ---------------- layer2 GEMM (64 nodes/block, 4x4 reg tile, fp16 out) + att coeffs ----------------
__global__ void k_gemm2(const float* __restrict__ W2) {
    __shared__ float Ws[4096];
    __shared__ float xs[4096];
    int t = threadIdx.x;
    int base = blockIdx.x * 64;
    for (int i = t; i < 4096; i += 256) {
        Ws[i] = W2[i];
        int gi = base * 64 + i;
        xs[i] = (gi < NN * 64) ? g_h1out[gi] : 0.f;
    }
    __syncthreads();
    int ct = t & 15, nt = t >> 4;
    float acc[4][4];
#pragma unroll
    for (int i = 0; i < 4; i++)
#pragma unroll
        for (int j = 0; j < 4; j++) acc[i][j] = 0.f;
#pragma unroll 8
    for (int k = 0; k < 64; k++) {
        float4 w = *(const float4*)&Ws[k * 64 + ct * 4];
#pragma unroll
        for (int i = 0; i < 4; i++) {
            float xv = xs[(nt * 4 + i) * 64 + k];
            acc[i][0] += xv * w.x; acc[i][1] += xv * w.y;
            acc[i][2] += xv * w.z; acc[i][3] += xv * w.w;
        }
    }
#pragma unroll
    for (int i = 0; i < 4; i++) {
        int node = base + nt * 4 + i;
        if (node < NN) {
            __half2 h0 = __floats2half2_rn(acc[i][0], acc[i][1]);
            __half2 h1 = __floats2half2_rn(acc[i][2], acc[i][3]);
            uint2 o;
            o.x = *(unsigned*)&h0;
            o.y = *(unsigned*)&h1;
            *(uint2*)&g_h2h[node * 32 + ct * 2] = o;
        }
    }
    if (t < 128) {
        int nl = t >> 1;
        bool isdst = t & 1;
        int node = base + nl;
        if (node < NN) {
            const float* u = g_u + 128 + (isdst ? 64 : 0);
            float a = 0.f;
#pragma unroll 16
            for (int k = 0; k < 64; k++) a += xs[nl * 64 + k] * u[k];
            if (isdst) g_adst2[node] = a; else g_asrc2[node] = a;
        }
    }
}

// ---------------- layer2 aggregation with inline exp, fp16 gathers ----------------
__global__ void k_agg2(const float* __restrict__ b2, float* __restrict__ out) {
    int warp = (blockIdx.x * blockDim.x + threadIdx.x) >> 5;
    int l = threadIdx.x & 31;
    if (warp >= NN) return;
    int n = warp;
    int p0 = g_offsets[n], p1 = g_offsets[n + 1];
    int d = p1 - p0;
    float adst2n = g_adst2[n];

    int   sa0 = 0,  sa1 = 0;
    float ea0 = 0.f, ea1 = 0.f;
    if (l < d) {
        sa0 = g_csr_src[p0 + l];
        ea0 = expf(lrelu(g_asrc2[sa0] + adst2n));
    }
    if (l + 32 < d) {
        sa1 = g_csr_src[p0 + l + 32];
        ea1 = expf(lrelu(g_asrc2[sa1] + adst2n));
    }

    float a0 = 0.f, a1 = 0.f, den = 0.f;
    int dmain = d < 64 ? d : 64;
#pragma unroll 4
    for (int j = 0; j < dmain; j++) {
        int   src = __shfl_sync(0xffffffffu, (j < 32) ? sa0 : sa1, j & 31);
        float ex  = __shfl_sync(0xffffffffu, (j < 32) ? ea0 : ea1, j & 31);
        den += ex;
        unsigned hv = g_h2h[src * 32 + l];
        float2 v = __half22float2(*(__half2*)&hv);
        a0 += ex * v.x;
        a1 += ex * v.y;
    }
    for (int j = 64; j < d; j++) {
        int src = g_csr_src[p0 + j];
        float ex = expf(lrelu(g_asrc2[src] + adst2n));
        den += ex;
        unsigned hv = g_h2h[src * 32 + l];
        float2 v = __half22float2(*(__half2*)&hv);
        a0 += ex * v.x;
        a1 += ex * v.y;
    }
    float inv = 1.f / (den + 1e-16f);
    float2 o;
    o.x = elu(a0 * inv + b2[2 * l + 0]);
    o.y = elu(a1 * inv + b2[2 * l + 1]);
    ((float2*)(out + n * 64))[l] = o;
}

// ---------------- launch ----------------
extern "C" void kernel_launch(void* const* d_in, const int* in_sizes, int n_in,
                              void* d_out, int out_size) {
    const float* x   = (const float*)d_in[0];
    const void*  ei  = d_in[1];
    const float* W1  = (const float*)d_in[2];
    const float* as1 = (const float*)d_in[3];
    const float* ad1 = (const float*)d_in[4];
    const float* b1  = (const float*)d_in[5];
    const float* W2  = (const float*)d_in[6];
    const float* as2 = (const float*)d_in[7];
    const float* ad2 = (const float*)d_in[8];
    const float* b2  = (const float*)d_in[9];
    float* out = (float*)d_out;

    k_init<<<1 + NB, 256>>>((const unsigned int*)ei, W1, as1, ad1, W2, as2, ad2);
    k_gemm1_hist<<<G1B + (ETOT + 255) / 256, 256>>>(x, W1, ei);
    k_scan_a<<<NB, 256>>>();
    k_scan_c<<<NB, 256>>>();
    k_scatter<<<(ETOT + 255) / 256, 256>>>(ei);
    k_agg1<<<NN / 8, 256>>>(b1);
    k_gemm2<<<G1B, 256>>>(W2);
    k_agg2<<<NN / 8, 256>>>(b2, out);
}

// round 8
// speedup vs baseline: 2.1556x; 1.1161x over previous
#include <cuda_runtime.h>
#include <cuda_fp16.h>

#define NN 50000
#define EE 400000
#define ETOT 450000            // EE + NN self loops
#define NB 196                 // ceil(NN/256)
#define G1B 782                // ceil(NN/64)

// ---------------- static scratch (no allocations allowed) ----------------
__device__ uint4    g_h1h[NN * 32];      // layer1 features fp16 [N,4,64]
__device__ float4   g_asrc1[NN];         // [N,4]
__device__ float4   g_adst1[NN];         // [N,4]
__device__ float    g_h1out[NN * 64];    // layer1 output after mean+bias+ELU
__device__ unsigned g_h2h[NN * 32];      // layer2 features fp16 [N,64] as 32 half2 words/node
__device__ float    g_asrc2[NN];
__device__ float    g_adst2[NN];
__device__ int      g_counts[NN];
__device__ int      g_offsets[NN + 1];
__device__ int      g_cursor[NN];
__device__ int      g_csr_src[ETOT];
__device__ int      g_bsum[256];
__device__ float    g_u[256];            // usrc1[64](k*4+h), udst1[64], usrc2[64], udst2[64]
__device__ int      g_is64;              // edge_index dtype flag

__device__ __forceinline__ float lrelu(float v) { return v > 0.f ? v : 0.2f * v; }
__device__ __forceinline__ float elu(float v)   { return v > 0.f ? v : expm1f(v); }

__device__ __forceinline__ int edge_val(const void* ei, int idx) {
    if (g_is64) return (int)((const long long*)ei)[idx];
    return ((const int*)ei)[idx];
}

__device__ __forceinline__ float pick4(float4 v, int s) {
    return (s == 0) ? v.x : (s == 1) ? v.y : (s == 2) ? v.z : v.w;
}

// ---------------- init: detect dtype + folded attention vectors + zero counts ----------------
__global__ void k_init(const unsigned int* __restrict__ ei32,
                       const float* __restrict__ W1, const float* __restrict__ as1,
                       const float* __restrict__ ad1, const float* __restrict__ W2,
                       const float* __restrict__ as2, const float* __restrict__ ad2) {
    int t = threadIdx.x;
    int b = blockIdx.x;
    if (b == 0) {
        if (t < 64) {
            int k = t >> 2, h = t & 3;
            float s = 0.f, d = 0.f;
            for (int c = 0; c < 64; c++) {
                float w = W1[k * 256 + h * 64 + c];
                s += w * as1[h * 64 + c];
                d += w * ad1[h * 64 + c];
            }
            g_u[k * 4 + h]      = s;
            g_u[64 + k * 4 + h] = d;
            float s2 = 0.f, d2 = 0.f;
            for (int c = 0; c < 64; c++) {
                float w = W2[t * 64 + c];
                s2 += w * as2[c];
                d2 += w * ad2[c];
            }
            g_u[128 + t] = s2;
            g_u[192 + t] = d2;
        } else if (t < 96) {
            int l = t - 64;
            unsigned a = ei32[2 * l + 1] | ei32[2 * (l + 32) + 1];
            unsigned nz = __ballot_sync(0xffffffffu, a != 0u);
            if (l == 0) g_is64 = (nz == 0u);
        }
    } else {
        int i = (b - 1) * 256 + t;
        if (i < NN) g_counts[i] = 0;
    }
}

// ---------------- fused: layer1 GEMM (64 nodes/block, 8x8 reg tile) + dst histogram ----------------
__global__ void k_gemm1_hist(const float* __restrict__ x, const float* __restrict__ W1,
                             const void* __restrict__ ei) {
    int t = threadIdx.x;
    int b = blockIdx.x;
    if (b < G1B) {
        __shared__ float Ws[4096];
        __shared__ float xs[1024];
        int base = b * 64;
        for (int i = t; i < 4096; i += 256) Ws[i] = W1[i];
        for (int i = t; i < 1024; i += 256) {
            int gi = base * 16 + i;
            xs[i] = (gi < NN * 16) ? x[gi] : 0.f;
        }
        __syncthreads();
        int ct = t & 31, nt = t >> 5;
        float acc[8][8];
#pragma unroll
        for (int i = 0; i < 8; i++)
#pragma unroll
            for (int j = 0; j < 8; j++) acc[i][j] = 0.f;
#pragma unroll
        for (int k = 0; k < 16; k++) {
            float4 wa = *(const float4*)&Ws[k * 256 + ct * 8];
            float4 wb = *(const float4*)&Ws[k * 256 + ct * 8 + 4];
#pragma unroll
            for (int i = 0; i < 8; i++) {
                float xv = xs[(nt * 8 + i) * 16 + k];
                acc[i][0] += xv * wa.x; acc[i][1] += xv * wa.y;
                acc[i][2] += xv * wa.z; acc[i][3] += xv * wa.w;
                acc[i][4] += xv * wb.x; acc[i][5] += xv * wb.y;
                acc[i][6] += xv * wb.z; acc[i][7] += xv * wb.w;
            }
        }
#pragma unroll
        for (int i = 0; i < 8; i++) {
            int node = base + nt * 8 + i;
            if (node < NN) {
                __half2 h0 = __floats2half2_rn(acc[i][0], acc[i][1]);
                __half2 h1 = __floats2half2_rn(acc[i][2], acc[i][3]);
                __half2 h2 = __floats2half2_rn(acc[i][4], acc[i][5]);
                __half2 h3 = __floats2half2_rn(acc[i][6], acc[i][7]);
                uint4 u;
                u.x = *(unsigned*)&h0; u.y = *(unsigned*)&h1;
                u.z = *(unsigned*)&h2; u.w = *(unsigned*)&h3;
                g_h1h[node * 32 + ct] = u;
            }
        }
        {
            int nl = t >> 2, h = t & 3;
            int node = base + nl;
            if (node < NN) {
                float s = 0.f, d = 0.f;
#pragma unroll
                for (int k = 0; k < 16; k++) {
                    float xv = xs[nl * 16 + k];
                    s += xv * g_u[k * 4 + h];
                    d += xv * g_u[64 + k * 4 + h];
                }
                ((float*)g_asrc1)[node * 4 + h] = s;
                ((float*)g_adst1)[node * 4 + h] = d;
            }
        }
    } else {
        int e = (b - G1B) * 256 + t;
        if (e < ETOT) {
            int dst = (e < EE) ? edge_val(ei, EE + e) : (e - EE);
            atomicAdd(&g_counts[dst], 1);
        }
    }
}

// ---------------- scan A: warp-shuffle block scan + block sums ----------------
__global__ void k_scan_a() {
    __shared__ int wsum[8];
    int t = threadIdx.x;
    int b = blockIdx.x;
    int i = b * 256 + t;
    int c = (i < NN) ? g_counts[i] : 0;
    int v = c;
#pragma unroll
    for (int o = 1; o < 32; o <<= 1) {
        int y = __shfl_up_sync(0xffffffffu, v, o);
        if ((t & 31) >= o) v += y;
    }
    if ((t & 31) == 31) wsum[t >> 5] = v;
    __syncthreads();
    if (t < 8) {
        int w = wsum[t];
#pragma unroll
        for (int o = 1; o < 8; o <<= 1) {
            int y = __shfl_up_sync(0x000000ffu, w, o);
            if (t >= o) w += y;
        }
        wsum[t] = w;
    }
    __syncthreads();
    int incl = v + ((t >= 32) ? wsum[(t >> 5) - 1] : 0);
    if (i < NN) g_offsets[i] = incl - c;
    if (t == 255) g_bsum[b] = incl;
}

// ---------------- scan C: inline top-level prefix (shuffle) + add-back ----------------
__global__ void k_scan_c() {
    __shared__ int wsum[8];
    __shared__ int bval;
    int t = threadIdx.x;
    int b = blockIdx.x;
    int c = (t < NB) ? g_bsum[t] : 0;
    int v = c;
#pragma unroll
    for (int o = 1; o < 32; o <<= 1) {
        int y = __shfl_up_sync(0xffffffffu, v, o);
        if ((t & 31) >= o) v += y;
    }
    if ((t & 31) == 31) wsum[t >> 5] = v;
    __syncthreads();
    if (t < 8) {
        int w = wsum[t];
#pragma unroll
        for (int o = 1; o < 8; o <<= 1) {
            int y = __shfl_up_sync(0x000000ffu, w, o);
            if (t >= o) w += y;
        }
        wsum[t] = w;
    }
    __syncthreads();
    int incl = v + ((t >= 32) ? wsum[(t >> 5) - 1] : 0);
    if (t == b) bval = incl - c;          // exclusive prefix for this block
    __syncthreads();
    int boff = bval;
    int i = b * 256 + t;
    if (i < NN) {
        int off = g_offsets[i] + boff;
        g_offsets[i] = off;
        g_cursor[i]  = off;
    }
    if (b == 0 && t == 0) g_offsets[NN] = ETOT;
}

// ---------------- scatter edges to CSR (src only) ----------------
__global__ void k_scatter(const void* __restrict__ ei) {
    int e = blockIdx.x * blockDim.x + threadIdx.x;
    if (e >= ETOT) return;
    int src, dst;
    if (e < EE) { src = edge_val(ei, e); dst = edge_val(ei, EE + e); }
    else        { src = e - EE; dst = e - EE; }
    int pos = atomicAdd(&g_cursor[dst], 1);
    g_csr_src[pos] = src;
}

// ---------------- layer1 aggregation: warp per node, batch-of-8 shared exp ----------------
// Lane l: head hsel = l>>3, batch slot el = l&7. Per 8-edge batch each lane computes
// ONE exp (its head, its slot's edge); the inner loop broadcasts (src, exh) via shfl.
__global__ void k_agg1(const float* __restrict__ b1) {
    int warp = (blockIdx.x * blockDim.x + threadIdx.x) >> 5;
    int l = threadIdx.x & 31;
    if (warp >= NN) return;
    int n = warp;
    int p0 = g_offsets[n], p1 = g_offsets[n + 1];
    int d = p1 - p0;
    int hsel = l >> 3;
    int el = l & 7;
    float adh = pick4(g_adst1[n], hsel);

    float acc[8] = {0,0,0,0,0,0,0,0};
    float den = 0.f;

    int base = 0;
    for (; base + 8 <= d; base += 8) {
        int s = g_csr_src[p0 + base + el];
        float ash = pick4(__ldg(&g_asrc1[s]), hsel);
        float ex = expf(lrelu(ash + adh));
#pragma unroll
        for (int j = 0; j < 8; j++) {
            int   src = __shfl_sync(0xffffffffu, s,  hsel * 8 + j);
            float exh = __shfl_sync(0xffffffffu, ex, hsel * 8 + j);
            den += exh;
            uint4 u = g_h1h[src * 32 + l];
            __half2* hh = (__half2*)&u;
            float2 v0 = __half22float2(hh[0]);
            float2 v1 = __half22float2(hh[1]);
            float2 v2 = __half22float2(hh[2]);
            float2 v3 = __half22float2(hh[3]);
            acc[0] += exh * v0.x; acc[1] += exh * v0.y;
            acc[2] += exh * v1.x; acc[3] += exh * v1.y;
            acc[4] += exh * v2.x; acc[5] += exh * v2.y;
            acc[6] += exh * v3.x; acc[7] += exh * v3.y;
        }
    }
    if (base < d) {
        int jm = d - base;
        int s = 0; float ex = 0.f;
        if (el < jm) {
            s = g_csr_src[p0 + base + el];
            float ash = pick4(__ldg(&g_asrc1[s]), hsel);
            ex = expf(lrelu(ash + adh));
        }
        for (int j = 0; j < jm; j++) {
            int   src = __shfl_sync(0xffffffffu, s,  hsel * 8 + j);
            float exh = __shfl_sync(0xffffffffu, ex, hsel * 8 + j);
            den += exh;
            uint4 u = g_h1h[src * 32 + l];
            __half2* hh = (__half2*)&u;
            float2 v0 = __half22float2(hh[0]);
            float2 v1 = __half22float2(hh[1]);
            float2 v2 = __half22float2(hh[2]);
            float2 v3 = __half22float2(hh[3]);
            acc[0] += exh * v0.x; acc[1] += exh * v0.y;
            acc[2] += exh * v1.x; acc[3] += exh * v1.y;
            acc[4] += exh * v2.x; acc[5] += exh * v2.y;
            acc[6] += exh * v3.x; acc[7] += exh * v3.y;
        }
    }

    float inv = 0.25f / (den + 1e-16f);
    float r[8];
#pragma unroll
    for (int j = 0; j < 8; j++) {
        r[j] = acc[j] * inv;
        r[j] += __shfl_xor_sync(0xffffffffu, r[j], 8);
        r[j] += __shfl_xor_sync(0xffffffffu, r[j], 16);
    }
    if (l < 8) {
        float4 o0, o1;
        o0.x = elu(r[0] + b1[l * 8 + 0]);
        o0.y = elu(r[1] + b1[l * 8 + 1]);
        o0.z = elu(r[2] + b1[l * 8 + 2]);
        o0.w = elu(r[3] + b1[l * 8 + 3]);
        o1.x = elu(r[4] + b1[l * 8 + 4]);
        o1.y = elu(r[5] + b1[l * 8 + 5]);
        o1.z = elu(r[6] + b1[l * 8 + 6]);
        o1.w = elu(r[7] + b1[l * 8 + 7]);
        float4* op = (float4*)(g_h1out + n * 64) + l * 2;
        op[0] = o0;
        op[1] = o1;
    }
}

// ---------------- layer2 GEMM (64 nodes/block, 4x4 reg tile, fp16 out) + att coeffs ----------------
__global__ void k_gemm2(const float* __restrict__ W2) {
    __shared__ float Ws[4096];
    __shared__ float xs[4096];
    int t = threadIdx.x;
    int base = blockIdx.x * 64;
    for (int i = t; i < 4096; i += 256) {
        Ws[i] = W2[i];
        int gi = base * 64 + i;
        xs[i] = (gi < NN * 64) ? g_h1out[gi] : 0.f;
    }
    __syncthreads();
    int ct = t & 15, nt = t >> 4;
    float acc[4][4];
#pragma unroll
    for (int i = 0; i < 4; i++)
#pragma unroll
        for (int j = 0; j < 4; j++) acc[i][j] = 0.f;
#pragma unroll 8
    for (int k = 0; k < 64; k++) {
        float4 w = *(const float4*)&Ws[k * 64 + ct * 4];
#pragma unroll
        for (int i = 0; i < 4; i++) {
            float xv = xs[(nt * 4 + i) * 64 + k];
            acc[i][0] += xv * w.x; acc[i][1] += xv * w.y;
            acc[i][2] += xv * w.z; acc[i][3] += xv * w.w;
        }
    }
#pragma unroll
    for (int i = 0; i < 4; i++) {
        int node = base + nt * 4 + i;
        if (node < NN) {
            __half2 h0 = __floats2half2_rn(acc[i][0], acc[i][1]);
            __half2 h1 = __floats2half2_rn(acc[i][2], acc[i][3]);
            uint2 o;
            o.x = *(unsigned*)&h0;
            o.y = *(unsigned*)&h1;
            *(uint2*)&g_h2h[node * 32 + ct * 2] = o;
        }
    }
    if (t < 128) {
        int nl = t >> 1;
        bool isdst = t & 1;
        int node = base + nl;
        if (node < NN) {
            const float* u = g_u + 128 + (isdst ? 64 : 0);
            float a = 0.f;
#pragma unroll 16
            for (int k = 0; k < 64; k++) a += xs[nl * 64 + k] * u[k];
            if (isdst) g_adst2[node] = a; else g_asrc2[node] = a;
        }
    }
}

// ---------------- layer2 aggregation with inline exp, fp16 gathers ----------------
__global__ void k_agg2(const float* __restrict__ b2, float* __restrict__ out) {
    int warp = (blockIdx.x * blockDim.x + threadIdx.x) >> 5;
    int l = threadIdx.x & 31;
    if (warp >= NN) return;
    int n = warp;
    int p0 = g_offsets[n], p1 = g_offsets[n + 1];
    int d = p1 - p0;
    float adst2n = g_adst2[n];

    int   sa0 = 0,  sa1 = 0;
    float ea0 = 0.f, ea1 = 0.f;
    if (l < d) {
        sa0 = g_csr_src[p0 + l];
        ea0 = expf(lrelu(g_asrc2[sa0] + adst2n));
    }
    if (l + 32 < d) {
        sa1 = g_csr_src[p0 + l + 32];
        ea1 = expf(lrelu(g_asrc2[sa1] + adst2n));
    }

    float a0 = 0.f, a1 = 0.f, den = 0.f;
    int dmain = d < 64 ? d : 64;
#pragma unroll 4
    for (int j = 0; j < dmain; j++) {
        int   src = __shfl_sync(0xffffffffu, (j < 32) ? sa0 : sa1, j & 31);
        float ex  = __shfl_sync(0xffffffffu, (j < 32) ? ea0 : ea1, j & 31);
        den += ex;
        unsigned hv = g_h2h[src * 32 + l];
        float2 v = __half22float2(*(__half2*)&hv);
        a0 += ex * v.x;
        a1 += ex * v.y;
    }
    for (int j = 64; j < d; j++) {
        int src = g_csr_src[p0 + j];
        float ex = expf(lrelu(g_asrc2[src] + adst2n));
        den += ex;
        unsigned hv = g_h2h[src * 32 + l];
        float2 v = __half22float2(*(__half2*)&hv);
        a0 += ex * v.x;
        a1 += ex * v.y;
    }
    float inv = 1.f / (den + 1e-16f);
    float2 o;
    o.x = elu(a0 * inv + b2[2 * l + 0]);
    o.y = elu(a1 * inv + b2[2 * l + 1]);
    ((float2*)(out + n * 64))[l] = o;
}

// ---------------- launch ----------------
extern "C" void kernel_launch(void* const* d_in, const int* in_sizes, int n_in,
                              void* d_out, int out_size) {
    const float* x   = (const float*)d_in[0];
    const void*  ei  = d_in[1];
    const float* W1  = (const float*)d_in[2];
    const float* as1 = (const float*)d_in[3];
    const float* ad1 = (const float*)d_in[4];
    const float* b1  = (const float*)d_in[5];
    const float* W2  = (const float*)d_in[6];
    const float* as2 = (const float*)d_in[7];
    const float* ad2 = (const float*)d_in[8];
    const float* b2  = (const float*)d_in[9];
    float* out = (float*)d_out;

    k_init<<<1 + NB, 256>>>((const unsigned int*)ei, W1, as1, ad1, W2, as2, ad2);
    k_gemm1_hist<<<G1B + (ETOT + 255) / 256, 256>>>(x, W1, ei);
    k_scan_a<<<NB, 256>>>();
    k_scan_c<<<NB, 256>>>();
    k_scatter<<<(ETOT + 255) / 256, 256>>>(ei);
    k_agg1<<<NN / 8, 256>>>(b1);
    k_gemm2<<<G1B, 256>>>(W2);
    k_agg2<<<NN / 8, 256>>>(b2, out);
}